// round 15
// baseline (speedup 1.0000x reference)
#include <cuda_runtime.h>
#include <cuda_bf16.h>
#include <math.h>
#include <stdint.h>

#define N_PTS   131072
#define N_FEATS 1000
#define FDIM    64
#define YSTR    104        // padded scratch row stride (100 valid + 4 zero pad)
#define CF      250
#define HID     128
#define AST     136        // bf16 row stride (17 x 16B units -> ldmatrix conflict-free)

// Scratch for [PE(36) | feats(64) | 0pad(4)] rows.
__device__ __align__(16) float g_y[(size_t)N_PTS * YSTR];
// Pre-converted weight images (smem layout: 128 rows x 136 bf16, zero-padded)
__device__ __align__(16) __nv_bfloat16 g_whi[4][128 * AST];
__device__ __align__(16) __nv_bfloat16 g_wlo[4][128 * AST];

__device__ __forceinline__ uint32_t smem_u32(const void* p) {
    uint32_t a;
    asm("{ .reg .u64 t; cvta.to.shared.u64 t, %1; cvt.u32.u64 %0, t; }" : "=r"(a) : "l"(p));
    return a;
}
__device__ __forceinline__ uint32_t pack_bf2(float a, float b) {
    __nv_bfloat162 t = __floats2bfloat162_rn(a, b);
    return *reinterpret_cast<uint32_t*>(&t);
}
__device__ __forceinline__ float snake(float h) {
    float sv = __sinf(h);
    return fmaf(0.5f, h, sv * sv);
}
__device__ __forceinline__ void ldm_x4(uint32_t& r0, uint32_t& r1, uint32_t& r2, uint32_t& r3,
                                       uint32_t addr) {
    asm volatile("ldmatrix.sync.aligned.m8n8.x4.shared.b16 {%0, %1, %2, %3}, [%4];"
                 : "=r"(r0), "=r"(r1), "=r"(r2), "=r"(r3) : "r"(addr));
}
__device__ __forceinline__ void mma_bf16(float* c, uint32_t a0, uint32_t a1, uint32_t a2,
                                         uint32_t a3, uint32_t b0, uint32_t b1) {
    asm volatile(
        "mma.sync.aligned.m16n8k16.row.col.f32.bf16.bf16.f32 "
        "{%0, %1, %2, %3}, {%4, %5, %6, %7}, {%8, %9}, {%0, %1, %2, %3};"
        : "+f"(c[0]), "+f"(c[1]), "+f"(c[2]), "+f"(c[3])
        : "r"(a0), "r"(a1), "r"(a2), "r"(a3), "r"(b0), "r"(b1));
}

// ---------------------------------------------------------------------------
// Kernel 0: convert W0..W3 (fp32) -> bf16 hi/lo smem-image layout in global.
// ---------------------------------------------------------------------------
__global__ void prep_kernel(const float* __restrict__ W0, const float* __restrict__ W1,
                            const float* __restrict__ W2, const float* __restrict__ W3)
{
    const int l = blockIdx.x;
    const float* W = (l == 0) ? W0 : (l == 1) ? W1 : (l == 2) ? W2 : W3;
    const int K = (l == 0) ? 100 : 128;
    for (int i = threadIdx.x; i < 128 * AST; i += 256) {
        int n = i / AST, k = i - n * AST;
        float w = (k < K) ? W[n * K + k] : 0.0f;
        __nv_bfloat16 wh = __float2bfloat16(w);
        g_whi[l][i] = wh;
        g_wlo[l][i] = __float2bfloat16(w - __bfloat162float(wh));
    }
}

// ---------------------------------------------------------------------------
// Kernel 1: distance softmax + weighted feature gather + PE
// ---------------------------------------------------------------------------
__global__ void __launch_bounds__(256, 2) attn_kernel(
    const float* __restrict__ x,
    const float* __restrict__ floc,
    const float* __restrict__ fvec)
{
    extern __shared__ float sm[];
    float* Mx = sm;
    float* My = sm + N_FEATS;
    float* Mz = sm + 2 * N_FEATS;
    float* Nn = sm + 3 * N_FEATS;
    float* Vs = sm + 4 * N_FEATS;

    const int tid = threadIdx.x;
    const int p   = blockIdx.x * 256 + tid;

    for (int i = tid; i < N_FEATS; i += 256) {
        float a = floc[3 * i + 0];
        float b = floc[3 * i + 1];
        float c = floc[3 * i + 2];
        Mx[i] = -2.0f * a; My[i] = -2.0f * b; Mz[i] = -2.0f * c;
        Nn[i] = a * a + b * b + c * c;
    }
    __syncthreads();

    const float x0 = x[3 * p + 0];
    const float x1 = x[3 * p + 1];
    const float x2 = x[3 * p + 2];
    const float xx = x0 * x0 + x1 * x1 + x2 * x2;

    float m = -1e30f;
    #pragma unroll 4
    for (int f = 0; f < N_FEATS; f++) {
        float d2 = fmaf(x2, Mz[f], fmaf(x1, My[f], fmaf(x0, Mx[f], xx + Nn[f])));
        d2 = fmaxf(d2, 0.0f);
        float inv = fminf(rsqrtf(d2), 1e6f);
        m = fmaxf(m, inv);
    }

    float s = 0.0f;
    float acc[FDIM];
    #pragma unroll
    for (int j = 0; j < FDIM; j++) acc[j] = 0.0f;

    for (int ch = 0; ch < N_FEATS / CF; ch++) {
        __syncthreads();
        const float4* src = (const float4*)(fvec + (size_t)ch * CF * FDIM);
        float4*       dst = (float4*)Vs;
        for (int i = tid; i < CF * FDIM / 4; i += 256) dst[i] = src[i];
        __syncthreads();

        const int base = ch * CF;
        #pragma unroll 1
        for (int f = 0; f < CF; f++) {
            const int g = base + f;
            float d2 = fmaf(x2, Mz[g], fmaf(x1, My[g], fmaf(x0, Mx[g], xx + Nn[g])));
            d2 = fmaxf(d2, 0.0f);
            float inv = fminf(rsqrtf(d2), 1e6f);
            float w = __expf(inv - m);
            s += w;
            const float4* vr = (const float4*)(Vs + f * FDIM);
            #pragma unroll
            for (int q = 0; q < 16; q++) {
                float4 v = vr[q];
                acc[4 * q + 0] = fmaf(w, v.x, acc[4 * q + 0]);
                acc[4 * q + 1] = fmaf(w, v.y, acc[4 * q + 1]);
                acc[4 * q + 2] = fmaf(w, v.z, acc[4 * q + 2]);
                acc[4 * q + 3] = fmaf(w, v.w, acc[4 * q + 3]);
            }
        }
    }

    const float invs = 1.0f / s;
    float4* y4 = (float4*)(g_y + (size_t)p * YSTR);

    #pragma unroll
    for (int q = 0; q < 16; q++)
        y4[9 + q] = make_float4(acc[4 * q + 0] * invs, acc[4 * q + 1] * invs,
                                acc[4 * q + 2] * invs, acc[4 * q + 3] * invs);
    y4[25] = make_float4(0.f, 0.f, 0.f, 0.f);   // zero pad cols 100..103

    float pe[36];
    const float freqs[6] = {3.14159274101257324f,  6.28318548202514648f,
                            12.5663709640502930f,  25.1327419281005859f,
                            50.2654838562011719f,  100.530967712402344f};
    const float xv[3] = {x0, x1, x2};
    #pragma unroll
    for (int d = 0; d < 3; d++) {
        #pragma unroll
        for (int l = 0; l < 6; l++) {
            float sv, cv;
            sincosf(xv[d] * freqs[l], &sv, &cv);
            pe[d * 12 + l]     = sv;
            pe[d * 12 + 6 + l] = cv;
        }
    }
    #pragma unroll
    for (int q = 0; q < 9; q++)
        y4[q] = make_float4(pe[4 * q], pe[4 * q + 1], pe[4 * q + 2], pe[4 * q + 3]);
}

// ---------------------------------------------------------------------------
// Kernel 2: warp-MMA bf16 (hi/lo 3-term) MLP. CTA = 128 points, 256 threads.
// SMEM: A_hi/A_lo [128][AST] bf16 (in-place across layers), W_hi/W_lo images,
// bias, W4. Warp w computes rows 16w..16w+15 x all 128 outputs (64 fp32 regs).
// ---------------------------------------------------------------------------
#define SO_AHI  0
#define SO_ALO  (128 * AST * 2)            // 34816
#define SO_WHI  (2 * 128 * AST * 2)        // 69632
#define SO_WLO  (3 * 128 * AST * 2)        // 104448
#define SO_BIAS (4 * 128 * AST * 2)        // 139264
#define SO_W4   (SO_BIAS + 512)
#define MLP_SMEM (SO_W4 + 512)             // 140288

__global__ void __launch_bounds__(256, 1) mlp_mma_kernel(
    const float* __restrict__ b0, const float* __restrict__ b1,
    const float* __restrict__ b2, const float* __restrict__ b3,
    const float* __restrict__ W4, const float* __restrict__ b4,
    float* __restrict__ out)
{
    extern __shared__ char smc[];
    const uint32_t sb = smem_u32(smc);
    float* bias = (float*)(smc + SO_BIAS);
    float* w4s  = (float*)(smc + SO_W4);

    const int tid  = threadIdx.x;
    const int wid  = tid >> 5;
    const int lane = tid & 31;
    const int qid  = lane >> 2;          // 0..7
    const int qtr  = lane & 3;           // 0..3
    const int p0   = blockIdx.x * 128;

    // ---- Prologue: stage A0 from g_y as bf16 hi/lo ----
    {
        const int row  = tid >> 1;
        const int cs   = (tid & 1) * 64;
        const float* yrow = g_y + (size_t)(p0 + row) * YSTR;
        char* ah = smc + SO_AHI + (row * AST + cs) * 2;
        char* al = smc + SO_ALO + (row * AST + cs) * 2;
        #pragma unroll
        for (int i = 0; i < 16; i++) {
            const int col = cs + 4 * i;
            float4 v = (col < YSTR) ? *(const float4*)(yrow + col)
                                    : make_float4(0.f, 0.f, 0.f, 0.f);
            uint32_t h0 = pack_bf2(v.x, v.y);
            uint32_t h1 = pack_bf2(v.z, v.w);
            __nv_bfloat162 hh0 = *reinterpret_cast<__nv_bfloat162*>(&h0);
            __nv_bfloat162 hh1 = *reinterpret_cast<__nv_bfloat162*>(&h1);
            uint32_t l0 = pack_bf2(v.x - __bfloat162float(hh0.x), v.y - __bfloat162float(hh0.y));
            uint32_t l1 = pack_bf2(v.z - __bfloat162float(hh1.x), v.w - __bfloat162float(hh1.y));
            *(uint32_t*)(ah + 8 * i)     = h0;
            *(uint32_t*)(ah + 8 * i + 4) = h1;
            *(uint32_t*)(al + 8 * i)     = l0;
            *(uint32_t*)(al + 8 * i + 4) = l1;
        }
    }

    // Per-lane ldmatrix base addresses
    const uint32_t a_base = sb + SO_AHI +
        (uint32_t)(((16 * wid + (lane & 15)) * AST + ((lane >> 4) << 3)) * 2);
    const uint32_t w_base = sb + SO_WHI +
        (uint32_t)((((lane & 7) + ((lane >> 4) << 3)) * AST + (((lane >> 3) & 1) << 3)) * 2);

    #pragma unroll 1
    for (int l = 0; l < 4; l++) {
        const float* bg = (l == 0) ? b0 : (l == 1) ? b1 : (l == 2) ? b2 : b3;

        __syncthreads();   // prev epilogue A-writes visible; prev W reads done
        // Stage W images (flat copy) + bias
        {
            const uint4* shi = (const uint4*)g_whi[l];
            const uint4* slo = (const uint4*)g_wlo[l];
            uint4* dhi = (uint4*)(smc + SO_WHI);
            uint4* dlo = (uint4*)(smc + SO_WLO);
            #pragma unroll
            for (int i = 0; i < 2176 / 256; i++) {   // 2176 uint4 per buffer
                dhi[tid + 256 * i] = shi[tid + 256 * i];
                dlo[tid + 256 * i] = slo[tid + 256 * i];
            }
            { int i = 2176 - 128; if (tid < 128) { dhi[tid + i] = shi[tid + i]; dlo[tid + i] = slo[tid + i]; } }
            if (tid < 128) bias[tid] = bg[tid];
            if (l == 3 && tid < 128) w4s[tid] = W4[tid];
        }
        __syncthreads();

        // ---- MMA phase: C[16 x 128] per warp, 3-term hi/lo ----
        float c[16][4];
        #pragma unroll
        for (int nt = 0; nt < 16; nt++)
            #pragma unroll
            for (int j = 0; j < 4; j++) c[nt][j] = 0.0f;

        #pragma unroll 2
        for (int kk = 0; kk < 8; kk++) {
            uint32_t ah0, ah1, ah2, ah3, al0, al1, al2, al3;
            ldm_x4(ah0, ah1, ah2, ah3, a_base + kk * 32);
            ldm_x4(al0, al1, al2, al3, a_base + (SO_ALO - SO_AHI) + kk * 32);
            #pragma unroll
            for (int np = 0; np < 8; np++) {
                const uint32_t wa = w_base + np * (16 * AST * 2) + kk * 32;
                uint32_t h00, h01, h10, h11, q00, q01, q10, q11;
                ldm_x4(h00, h01, h10, h11, wa);
                ldm_x4(q00, q01, q10, q11, wa + (SO_WLO - SO_WHI));
                mma_bf16(c[2 * np],     ah0, ah1, ah2, ah3, h00, h01);
                mma_bf16(c[2 * np + 1], ah0, ah1, ah2, ah3, h10, h11);
                mma_bf16(c[2 * np],     al0, al1, al2, al3, h00, h01);
                mma_bf16(c[2 * np + 1], al0, al1, al2, al3, h10, h11);
                mma_bf16(c[2 * np],     ah0, ah1, ah2, ah3, q00, q01);
                mma_bf16(c[2 * np + 1], ah0, ah1, ah2, ah3, q10, q11);
            }
        }
        __syncthreads();   // all A/W reads done before epilogue overwrites A

        if (l < 3) {
            // bias + snake -> repack hi/lo -> in-place A store
            const int r0 = 16 * wid + qid;
            #pragma unroll
            for (int nt = 0; nt < 16; nt++) {
                const int col = 8 * nt + 2 * qtr;
                const float bb0 = bias[col], bb1 = bias[col + 1];
                float v0 = snake(c[nt][0] + bb0);
                float v1 = snake(c[nt][1] + bb1);
                float v2 = snake(c[nt][2] + bb0);
                float v3 = snake(c[nt][3] + bb1);
                uint32_t h0 = pack_bf2(v0, v1);
                uint32_t h2 = pack_bf2(v2, v3);
                __nv_bfloat162 hh0 = *reinterpret_cast<__nv_bfloat162*>(&h0);
                __nv_bfloat162 hh2 = *reinterpret_cast<__nv_bfloat162*>(&h2);
                uint32_t l0 = pack_bf2(v0 - __bfloat162float(hh0.x), v1 - __bfloat162float(hh0.y));
                uint32_t l2 = pack_bf2(v2 - __bfloat162float(hh2.x), v3 - __bfloat162float(hh2.y));
                *(uint32_t*)(smc + SO_AHI + (r0 * AST + col) * 2)       = h0;
                *(uint32_t*)(smc + SO_AHI + ((r0 + 8) * AST + col) * 2) = h2;
                *(uint32_t*)(smc + SO_ALO + (r0 * AST + col) * 2)       = l0;
                *(uint32_t*)(smc + SO_ALO + ((r0 + 8) * AST + col) * 2) = l2;
            }
        } else {
            // Output layer fused: dot(snake(h + bias), W4), quad reduce
            float s0 = 0.0f, s1 = 0.0f;
            #pragma unroll
            for (int nt = 0; nt < 16; nt++) {
                const int col = 8 * nt + 2 * qtr;
                const float bb0 = bias[col], bb1 = bias[col + 1];
                const float w40 = w4s[col],  w41 = w4s[col + 1];
                s0 = fmaf(snake(c[nt][0] + bb0), w40, s0);
                s0 = fmaf(snake(c[nt][1] + bb1), w41, s0);
                s1 = fmaf(snake(c[nt][2] + bb0), w40, s1);
                s1 = fmaf(snake(c[nt][3] + bb1), w41, s1);
            }
            s0 += __shfl_xor_sync(0xFFFFFFFF, s0, 1);
            s0 += __shfl_xor_sync(0xFFFFFFFF, s0, 2);
            s1 += __shfl_xor_sync(0xFFFFFFFF, s1, 1);
            s1 += __shfl_xor_sync(0xFFFFFFFF, s1, 2);
            if (qtr == 0) {
                const float bb4 = __ldg(b4);
                const int r0 = 16 * wid + qid;
                out[p0 + r0]     = s0 + bb4;
                out[p0 + r0 + 8] = s1 + bb4;
            }
        }
    }
}

// ---------------------------------------------------------------------------
extern "C" void kernel_launch(void* const* d_in, const int* in_sizes, int n_in,
                              void* d_out, int out_size)
{
    const float* x  = (const float*)d_in[0];
    const float* fl = (const float*)d_in[1];
    const float* fv = (const float*)d_in[2];
    const float* W0 = (const float*)d_in[3];
    const float* b0 = (const float*)d_in[4];
    const float* W1 = (const float*)d_in[5];
    const float* b1 = (const float*)d_in[6];
    const float* W2 = (const float*)d_in[7];
    const float* b2 = (const float*)d_in[8];
    const float* W3 = (const float*)d_in[9];
    const float* b3 = (const float*)d_in[10];
    const float* W4 = (const float*)d_in[11];
    const float* b4 = (const float*)d_in[12];
    float* out = (float*)d_out;

    const size_t sm1 = (size_t)(4 * N_FEATS + CF * FDIM) * sizeof(float);   // 80000 B

    cudaFuncSetAttribute(attn_kernel,    cudaFuncAttributeMaxDynamicSharedMemorySize, (int)sm1);
    cudaFuncSetAttribute(mlp_mma_kernel, cudaFuncAttributeMaxDynamicSharedMemorySize, MLP_SMEM);

    prep_kernel<<<4, 256>>>(W0, W1, W2, W3);
    attn_kernel<<<N_PTS / 256, 256, sm1>>>(x, fl, fv);
    mlp_mma_kernel<<<N_PTS / 128, 256, MLP_SMEM>>>(b0, b1, b2, b3, W4, b4, out);
}

// round 16
// speedup vs baseline: 2.2015x; 2.2015x over previous
#include <cuda_runtime.h>
#include <cuda_bf16.h>
#include <math.h>
#include <stdint.h>

#define N_PTS   131072
#define N_FEATS 1000
#define FDIM    64
#define YSTR    104        // padded scratch row stride (100 valid + 4 zero pad)
#define HID     128
#define AST     136        // bf16 row stride (17 x 16B -> ldmatrix conflict-free)

// Scratch for [PE(36) | feats(64) | 0pad(4)] rows.
__device__ __align__(16) float g_y[(size_t)N_PTS * YSTR];
// Pre-converted MLP weight images (128 rows x 136 bf16, zero-padded)
__device__ __align__(16) __nv_bfloat16 g_whi[4][128 * AST];
__device__ __align__(16) __nv_bfloat16 g_wlo[4][128 * AST];
// Pre-converted V^T chunk images: [chunk][hi/lo][64 dims x 136 k] bf16
__device__ __align__(16) __nv_bfloat16 g_vt[8][2][64 * AST];

__device__ __forceinline__ uint32_t smem_u32(const void* p) {
    uint32_t a;
    asm("{ .reg .u64 t; cvta.to.shared.u64 t, %1; cvt.u32.u64 %0, t; }" : "=r"(a) : "l"(p));
    return a;
}
__device__ __forceinline__ uint32_t pack_bf2(float a, float b) {
    __nv_bfloat162 t = __floats2bfloat162_rn(a, b);
    return *reinterpret_cast<uint32_t*>(&t);
}
__device__ __forceinline__ float snake(float h) {
    float sv = __sinf(h);
    return fmaf(0.5f, h, sv * sv);
}
__device__ __forceinline__ void ldm_x4(uint32_t& r0, uint32_t& r1, uint32_t& r2, uint32_t& r3,
                                       uint32_t addr) {
    asm volatile("ldmatrix.sync.aligned.m8n8.x4.shared.b16 {%0, %1, %2, %3}, [%4];"
                 : "=r"(r0), "=r"(r1), "=r"(r2), "=r"(r3) : "r"(addr));
}
__device__ __forceinline__ void mma_bf16(float* c, uint32_t a0, uint32_t a1, uint32_t a2,
                                         uint32_t a3, uint32_t b0, uint32_t b1) {
    asm volatile(
        "mma.sync.aligned.m16n8k16.row.col.f32.bf16.bf16.f32 "
        "{%0, %1, %2, %3}, {%4, %5, %6, %7}, {%8, %9}, {%0, %1, %2, %3};"
        : "+f"(c[0]), "+f"(c[1]), "+f"(c[2]), "+f"(c[3])
        : "r"(a0), "r"(a1), "r"(a2), "r"(a3), "r"(b0), "r"(b1));
}

// ---------------------------------------------------------------------------
// Kernel 0: convert W0..W3 and V^T chunks to bf16 hi/lo images. grid=24.
// ---------------------------------------------------------------------------
__global__ void prep_kernel(const float* __restrict__ W0, const float* __restrict__ W1,
                            const float* __restrict__ W2, const float* __restrict__ W3,
                            const float* __restrict__ fvec)
{
    const int b = blockIdx.x;
    if (b < 16) {
        const int l = b >> 2, part = b & 3;
        const float* W = (l == 0) ? W0 : (l == 1) ? W1 : (l == 2) ? W2 : W3;
        const int K = (l == 0) ? 100 : 128;
        const int i0 = part * 32 * AST, i1 = i0 + 32 * AST;
        for (int i = i0 + threadIdx.x; i < i1; i += 256) {
            int n = i / AST, k = i - n * AST;
            float w = (k < K) ? W[n * K + k] : 0.0f;
            __nv_bfloat16 wh = __float2bfloat16(w);
            g_whi[l][i] = wh;
            g_wlo[l][i] = __float2bfloat16(w - __bfloat162float(wh));
        }
    } else {
        const int c = b - 16;   // 0..7
        for (int i = threadIdx.x; i < 64 * AST; i += 256) {
            int n = i / AST, k = i - n * AST;
            int g = 128 * c + k;
            float v = (k < 128 && g < N_FEATS) ? fvec[g * FDIM + n] : 0.0f;
            __nv_bfloat16 vh = __float2bfloat16(v);
            g_vt[c][0][i] = vh;
            g_vt[c][1][i] = __float2bfloat16(v - __bfloat162float(vh));
        }
    }
}

// ---------------------------------------------------------------------------
// Kernel 1: tensor-core attention. CTA = 128 points, 256 threads.
// Scores computed per-lane directly into MMA A-fragments (no P smem).
// P@V via 3-term hi/lo bf16 HMMA; V^T chunks double-buffered in smem.
// ---------------------------------------------------------------------------
#define SA_LOC 0                       // float4[1024]: (-2lx,-2ly,-2lz,|l|^2), pads 0
#define SA_X   16384                   // float4[128]:  (x0,x1,x2,|x|^2)
#define SA_VT  18432                   // 2 buffers x (hi 17408 B + lo 17408 B)
#define VT_BUF 34816
#define ATT_SMEM (SA_VT + 2 * VT_BUF)  // 88064

__global__ void __launch_bounds__(256, 2) attn_mma_kernel(
    const float* __restrict__ x,
    const float* __restrict__ floc)
{
    extern __shared__ char smc[];
    const uint32_t sb = smem_u32(smc);
    float4* Loc4 = (float4*)(smc + SA_LOC);
    float4* X4   = (float4*)(smc + SA_X);

    const int tid  = threadIdx.x;
    const int wid  = tid >> 5;
    const int lane = tid & 31;
    const int qid  = lane >> 2;
    const int qtr  = lane & 3;
    const int p0   = blockIdx.x * 128;

    // Stage locations (pre-scaled) + per-point x
    for (int i = tid; i < 1024; i += 256) {
        float4 L = make_float4(0.f, 0.f, 0.f, 0.f);
        if (i < N_FEATS) {
            float a = floc[3 * i + 0], b = floc[3 * i + 1], c = floc[3 * i + 2];
            L = make_float4(-2.f * a, -2.f * b, -2.f * c, a * a + b * b + c * c);
        }
        Loc4[i] = L;
    }
    if (tid < 128) {
        float a = x[3 * (p0 + tid) + 0];
        float b = x[3 * (p0 + tid) + 1];
        float c = x[3 * (p0 + tid) + 2];
        X4[tid] = make_float4(a, b, c, a * a + b * b + c * c);
    }
    __syncthreads();

    const int r0 = 16 * wid + qid;          // this lane's rows: r0, r0+8
    const float4 xa = X4[r0];
    const float4 xb = X4[r0 + 8];

    // ---- Pass 1: min d2 per row (pure FMA; rsqrt once at end) ----
    float d2m0 = 1e30f, d2m1 = 1e30f;
    {
        const float4* Lp = Loc4 + qtr * 250;
        #pragma unroll 2
        for (int i = 0; i < 250; i++) {
            float4 L = Lp[i];
            float da = fmaf(xa.x, L.x, fmaf(xa.y, L.y, fmaf(xa.z, L.z, xa.w + L.w)));
            float db = fmaf(xb.x, L.x, fmaf(xb.y, L.y, fmaf(xb.z, L.z, xb.w + L.w)));
            d2m0 = fminf(d2m0, da);
            d2m1 = fminf(d2m1, db);
        }
    }
    d2m0 = fminf(d2m0, __shfl_xor_sync(0xFFFFFFFF, d2m0, 1));
    d2m0 = fminf(d2m0, __shfl_xor_sync(0xFFFFFFFF, d2m0, 2));
    d2m1 = fminf(d2m1, __shfl_xor_sync(0xFFFFFFFF, d2m1, 1));
    d2m1 = fminf(d2m1, __shfl_xor_sync(0xFFFFFFFF, d2m1, 2));
    const float m0 = fminf(rsqrtf(fmaxf(d2m0, 0.f)), 1e6f);
    const float m1 = fminf(rsqrtf(fmaxf(d2m1, 0.f)), 1e6f);

    // ---- Chunk loop: scores -> A frags (regs), MMA vs V^T (smem) ----
    float s0 = 0.f, s1 = 0.f;
    float cfr[8][4];
    #pragma unroll
    for (int nt = 0; nt < 8; nt++)
        #pragma unroll
        for (int j = 0; j < 4; j++) cfr[nt][j] = 0.f;

    // preload chunk 0 into buffer 0
    {
        const uint4* src = (const uint4*)g_vt[0];
        uint4* dst = (uint4*)(smc + SA_VT);
        for (int i = tid; i < VT_BUF / 16; i += 256) dst[i] = src[i];
    }
    __syncthreads();

    #pragma unroll 1
    for (int ch = 0; ch < 8; ch++) {
        if (ch < 7) {   // prefetch next chunk into other buffer
            const uint4* src = (const uint4*)g_vt[ch + 1];
            uint4* dst = (uint4*)(smc + SA_VT + ((ch + 1) & 1) * VT_BUF);
            for (int i = tid; i < VT_BUF / 16; i += 256) dst[i] = src[i];
        }
        const uint32_t vb = sb + SA_VT + (ch & 1) * VT_BUF;
        const uint32_t v_base = vb +
            (uint32_t)((((lane & 7) + ((lane >> 4) << 3)) * AST + (((lane >> 3) & 1) << 3)) * 2);

        #pragma unroll 2
        for (int kk = 0; kk < 8; kk++) {
            const int g0 = 128 * ch + 16 * kk + 2 * qtr;  // k indices g0,g0+1,g0+8,g0+9
            float4 L0 = Loc4[g0], L1 = Loc4[g0 + 1], L8 = Loc4[g0 + 8], L9 = Loc4[g0 + 9];

            float wa0, wa1, wa8, wa9, wb0, wb1, wb8, wb9;
            {
                float d;
                d = fmaf(xa.x, L0.x, fmaf(xa.y, L0.y, fmaf(xa.z, L0.z, xa.w + L0.w)));
                wa0 = __expf(fminf(rsqrtf(fmaxf(d, 0.f)), 1e6f) - m0);
                d = fmaf(xa.x, L1.x, fmaf(xa.y, L1.y, fmaf(xa.z, L1.z, xa.w + L1.w)));
                wa1 = __expf(fminf(rsqrtf(fmaxf(d, 0.f)), 1e6f) - m0);
                d = fmaf(xa.x, L8.x, fmaf(xa.y, L8.y, fmaf(xa.z, L8.z, xa.w + L8.w)));
                wa8 = __expf(fminf(rsqrtf(fmaxf(d, 0.f)), 1e6f) - m0);
                d = fmaf(xa.x, L9.x, fmaf(xa.y, L9.y, fmaf(xa.z, L9.z, xa.w + L9.w)));
                wa9 = __expf(fminf(rsqrtf(fmaxf(d, 0.f)), 1e6f) - m0);
                d = fmaf(xb.x, L0.x, fmaf(xb.y, L0.y, fmaf(xb.z, L0.z, xb.w + L0.w)));
                wb0 = __expf(fminf(rsqrtf(fmaxf(d, 0.f)), 1e6f) - m1);
                d = fmaf(xb.x, L1.x, fmaf(xb.y, L1.y, fmaf(xb.z, L1.z, xb.w + L1.w)));
                wb1 = __expf(fminf(rsqrtf(fmaxf(d, 0.f)), 1e6f) - m1);
                d = fmaf(xb.x, L8.x, fmaf(xb.y, L8.y, fmaf(xb.z, L8.z, xb.w + L8.w)));
                wb8 = __expf(fminf(rsqrtf(fmaxf(d, 0.f)), 1e6f) - m1);
                d = fmaf(xb.x, L9.x, fmaf(xb.y, L9.y, fmaf(xb.z, L9.z, xb.w + L9.w)));
                wb9 = __expf(fminf(rsqrtf(fmaxf(d, 0.f)), 1e6f) - m1);
            }
            if (g0 + 9 >= N_FEATS) {   // tail padding (only chunk 7)
                if (g0     >= N_FEATS) { wa0 = 0.f; wb0 = 0.f; }
                if (g0 + 1 >= N_FEATS) { wa1 = 0.f; wb1 = 0.f; }
                if (g0 + 8 >= N_FEATS) { wa8 = 0.f; wb8 = 0.f; }
                wa9 = (g0 + 9 < N_FEATS) ? wa9 : 0.f;
                wb9 = (g0 + 9 < N_FEATS) ? wb9 : 0.f;
            }
            s0 += (wa0 + wa1) + (wa8 + wa9);
            s1 += (wb0 + wb1) + (wb8 + wb9);

            // A fragments (m16n8k16 row-major): hi and lo
            uint32_t ah0 = pack_bf2(wa0, wa1);
            uint32_t ah1 = pack_bf2(wb0, wb1);
            uint32_t ah2 = pack_bf2(wa8, wa9);
            uint32_t ah3 = pack_bf2(wb8, wb9);
            __nv_bfloat162 h;
            h = *reinterpret_cast<__nv_bfloat162*>(&ah0);
            uint32_t al0 = pack_bf2(wa0 - __bfloat162float(h.x), wa1 - __bfloat162float(h.y));
            h = *reinterpret_cast<__nv_bfloat162*>(&ah1);
            uint32_t al1 = pack_bf2(wb0 - __bfloat162float(h.x), wb1 - __bfloat162float(h.y));
            h = *reinterpret_cast<__nv_bfloat162*>(&ah2);
            uint32_t al2 = pack_bf2(wa8 - __bfloat162float(h.x), wa9 - __bfloat162float(h.y));
            h = *reinterpret_cast<__nv_bfloat162*>(&ah3);
            uint32_t al3 = pack_bf2(wb8 - __bfloat162float(h.x), wb9 - __bfloat162float(h.y));

            #pragma unroll
            for (int np = 0; np < 4; np++) {
                const uint32_t va = v_base + np * (16 * AST * 2) + kk * 32;
                uint32_t h0, h1, h2, h3, q0, q1, q2, q3;
                ldm_x4(h0, h1, h2, h3, va);             // V hi: n-tiles 2np, 2np+1
                ldm_x4(q0, q1, q2, q3, va + 17408);     // V lo
                mma_bf16(cfr[2 * np],     ah0, ah1, ah2, ah3, h0, h1);
                mma_bf16(cfr[2 * np + 1], ah0, ah1, ah2, ah3, h2, h3);
                mma_bf16(cfr[2 * np],     al0, al1, al2, al3, h0, h1);
                mma_bf16(cfr[2 * np + 1], al0, al1, al2, al3, h2, h3);
                mma_bf16(cfr[2 * np],     ah0, ah1, ah2, ah3, q0, q1);
                mma_bf16(cfr[2 * np + 1], ah0, ah1, ah2, ah3, q2, q3);
            }
        }
        __syncthreads();
    }

    // ---- Epilogue: normalize, write feats to g_y ----
    s0 += __shfl_xor_sync(0xFFFFFFFF, s0, 1);
    s0 += __shfl_xor_sync(0xFFFFFFFF, s0, 2);
    s1 += __shfl_xor_sync(0xFFFFFFFF, s1, 1);
    s1 += __shfl_xor_sync(0xFFFFFFFF, s1, 2);
    const float is0 = 1.0f / s0;
    const float is1 = 1.0f / s1;

    float* ya = g_y + (size_t)(p0 + r0) * YSTR;
    float* yb = g_y + (size_t)(p0 + r0 + 8) * YSTR;
    #pragma unroll
    for (int nt = 0; nt < 8; nt++) {
        const int col = 36 + 8 * nt + 2 * qtr;
        *(float2*)(ya + col) = make_float2(cfr[nt][0] * is0, cfr[nt][1] * is0);
        *(float2*)(yb + col) = make_float2(cfr[nt][2] * is1, cfr[nt][3] * is1);
    }

    // ---- PE + zero pad (one thread per point) ----
    if (tid < 128) {
        const float4 xv = X4[tid];
        float pe[36];
        const float freqs[6] = {3.14159274101257324f,  6.28318548202514648f,
                                12.5663709640502930f,  25.1327419281005859f,
                                50.2654838562011719f,  100.530967712402344f};
        const float xs[3] = {xv.x, xv.y, xv.z};
        #pragma unroll
        for (int d = 0; d < 3; d++) {
            #pragma unroll
            for (int l = 0; l < 6; l++) {
                float sv, cv;
                sincosf(xs[d] * freqs[l], &sv, &cv);
                pe[d * 12 + l]     = sv;
                pe[d * 12 + 6 + l] = cv;
            }
        }
        float4* y4 = (float4*)(g_y + (size_t)(p0 + tid) * YSTR);
        #pragma unroll
        for (int q = 0; q < 9; q++)
            y4[q] = make_float4(pe[4 * q], pe[4 * q + 1], pe[4 * q + 2], pe[4 * q + 3]);
        y4[25] = make_float4(0.f, 0.f, 0.f, 0.f);
    }
}

// ---------------------------------------------------------------------------
// Kernel 2: warp-MMA bf16 (hi/lo 3-term) MLP. CTA = 128 points, 256 threads.
// (unchanged from R15)
// ---------------------------------------------------------------------------
#define SO_AHI  0
#define SO_ALO  (128 * AST * 2)
#define SO_WHI  (2 * 128 * AST * 2)
#define SO_WLO  (3 * 128 * AST * 2)
#define SO_BIAS (4 * 128 * AST * 2)
#define SO_W4   (SO_BIAS + 512)
#define MLP_SMEM (SO_W4 + 512)

__global__ void __launch_bounds__(256, 1) mlp_mma_kernel(
    const float* __restrict__ b0, const float* __restrict__ b1,
    const float* __restrict__ b2, const float* __restrict__ b3,
    const float* __restrict__ W4, const float* __restrict__ b4,
    float* __restrict__ out)
{
    extern __shared__ char smc[];
    const uint32_t sb = smem_u32(smc);
    float* bias = (float*)(smc + SO_BIAS);
    float* w4s  = (float*)(smc + SO_W4);

    const int tid  = threadIdx.x;
    const int wid  = tid >> 5;
    const int lane = tid & 31;
    const int qid  = lane >> 2;
    const int qtr  = lane & 3;
    const int p0   = blockIdx.x * 128;

    // Prologue: stage A0 from g_y as bf16 hi/lo
    {
        const int row  = tid >> 1;
        const int cs   = (tid & 1) * 64;
        const float* yrow = g_y + (size_t)(p0 + row) * YSTR;
        char* ah = smc + SO_AHI + (row * AST + cs) * 2;
        char* al = smc + SO_ALO + (row * AST + cs) * 2;
        #pragma unroll
        for (int i = 0; i < 16; i++) {
            const int col = cs + 4 * i;
            float4 v = (col < YSTR) ? *(const float4*)(yrow + col)
                                    : make_float4(0.f, 0.f, 0.f, 0.f);
            uint32_t h0 = pack_bf2(v.x, v.y);
            uint32_t h1 = pack_bf2(v.z, v.w);
            __nv_bfloat162 hh0 = *reinterpret_cast<__nv_bfloat162*>(&h0);
            __nv_bfloat162 hh1 = *reinterpret_cast<__nv_bfloat162*>(&h1);
            uint32_t l0 = pack_bf2(v.x - __bfloat162float(hh0.x), v.y - __bfloat162float(hh0.y));
            uint32_t l1 = pack_bf2(v.z - __bfloat162float(hh1.x), v.w - __bfloat162float(hh1.y));
            *(uint32_t*)(ah + 8 * i)     = h0;
            *(uint32_t*)(ah + 8 * i + 4) = h1;
            *(uint32_t*)(al + 8 * i)     = l0;
            *(uint32_t*)(al + 8 * i + 4) = l1;
        }
    }

    const uint32_t a_base = sb + SO_AHI +
        (uint32_t)(((16 * wid + (lane & 15)) * AST + ((lane >> 4) << 3)) * 2);
    const uint32_t w_base = sb + SO_WHI +
        (uint32_t)((((lane & 7) + ((lane >> 4) << 3)) * AST + (((lane >> 3) & 1) << 3)) * 2);

    #pragma unroll 1
    for (int l = 0; l < 4; l++) {
        const float* bg = (l == 0) ? b0 : (l == 1) ? b1 : (l == 2) ? b2 : b3;

        __syncthreads();
        {
            const uint4* shi = (const uint4*)g_whi[l];
            const uint4* slo = (const uint4*)g_wlo[l];
            uint4* dhi = (uint4*)(smc + SO_WHI);
            uint4* dlo = (uint4*)(smc + SO_WLO);
            #pragma unroll
            for (int i = 0; i < 2176 / 256; i++) {
                dhi[tid + 256 * i] = shi[tid + 256 * i];
                dlo[tid + 256 * i] = slo[tid + 256 * i];
            }
            { int i = 2176 - 128; if (tid < 128) { dhi[tid + i] = shi[tid + i]; dlo[tid + i] = slo[tid + i]; } }
            if (tid < 128) bias[tid] = bg[tid];
            if (l == 3 && tid < 128) w4s[tid] = W4[tid];
        }
        __syncthreads();

        float c[16][4];
        #pragma unroll
        for (int nt = 0; nt < 16; nt++)
            #pragma unroll
            for (int j = 0; j < 4; j++) c[nt][j] = 0.0f;

        #pragma unroll 2
        for (int kk = 0; kk < 8; kk++) {
            uint32_t ah0, ah1, ah2, ah3, al0, al1, al2, al3;
            ldm_x4(ah0, ah1, ah2, ah3, a_base + kk * 32);
            ldm_x4(al0, al1, al2, al3, a_base + (SO_ALO - SO_AHI) + kk * 32);
            #pragma unroll
            for (int np = 0; np < 8; np++) {
                const uint32_t wa = w_base + np * (16 * AST * 2) + kk * 32;
                uint32_t h00, h01, h10, h11, q00, q01, q10, q11;
                ldm_x4(h00, h01, h10, h11, wa);
                ldm_x4(q00, q01, q10, q11, wa + (SO_WLO - SO_WHI));
                mma_bf16(c[2 * np],     ah0, ah1, ah2, ah3, h00, h01);
                mma_bf16(c[2 * np + 1], ah0, ah1, ah2, ah3, h10, h11);
                mma_bf16(c[2 * np],     al0, al1, al2, al3, h00, h01);
                mma_bf16(c[2 * np + 1], al0, al1, al2, al3, h10, h11);
                mma_bf16(c[2 * np],     ah0, ah1, ah2, ah3, q00, q01);
                mma_bf16(c[2 * np + 1], ah0, ah1, ah2, ah3, q10, q11);
            }
        }
        __syncthreads();

        if (l < 3) {
            const int r0 = 16 * wid + qid;
            #pragma unroll
            for (int nt = 0; nt < 16; nt++) {
                const int col = 8 * nt + 2 * qtr;
                const float bb0 = bias[col], bb1 = bias[col + 1];
                float v0 = snake(c[nt][0] + bb0);
                float v1 = snake(c[nt][1] + bb1);
                float v2 = snake(c[nt][2] + bb0);
                float v3 = snake(c[nt][3] + bb1);
                uint32_t h0 = pack_bf2(v0, v1);
                uint32_t h2 = pack_bf2(v2, v3);
                __nv_bfloat162 hh0 = *reinterpret_cast<__nv_bfloat162*>(&h0);
                __nv_bfloat162 hh2 = *reinterpret_cast<__nv_bfloat162*>(&h2);
                uint32_t l0 = pack_bf2(v0 - __bfloat162float(hh0.x), v1 - __bfloat162float(hh0.y));
                uint32_t l2 = pack_bf2(v2 - __bfloat162float(hh2.x), v3 - __bfloat162float(hh2.y));
                *(uint32_t*)(smc + SO_AHI + (r0 * AST + col) * 2)       = h0;
                *(uint32_t*)(smc + SO_AHI + ((r0 + 8) * AST + col) * 2) = h2;
                *(uint32_t*)(smc + SO_ALO + (r0 * AST + col) * 2)       = l0;
                *(uint32_t*)(smc + SO_ALO + ((r0 + 8) * AST + col) * 2) = l2;
            }
        } else {
            float s0 = 0.0f, s1 = 0.0f;
            #pragma unroll
            for (int nt = 0; nt < 16; nt++) {
                const int col = 8 * nt + 2 * qtr;
                const float bb0 = bias[col], bb1 = bias[col + 1];
                const float w40 = w4s[col],  w41 = w4s[col + 1];
                s0 = fmaf(snake(c[nt][0] + bb0), w40, s0);
                s0 = fmaf(snake(c[nt][1] + bb1), w41, s0);
                s1 = fmaf(snake(c[nt][2] + bb0), w40, s1);
                s1 = fmaf(snake(c[nt][3] + bb1), w41, s1);
            }
            s0 += __shfl_xor_sync(0xFFFFFFFF, s0, 1);
            s0 += __shfl_xor_sync(0xFFFFFFFF, s0, 2);
            s1 += __shfl_xor_sync(0xFFFFFFFF, s1, 1);
            s1 += __shfl_xor_sync(0xFFFFFFFF, s1, 2);
            if (qtr == 0) {
                const float bb4 = __ldg(b4);
                const int r0 = 16 * wid + qid;
                out[p0 + r0]     = s0 + bb4;
                out[p0 + r0 + 8] = s1 + bb4;
            }
        }
    }
}

// ---------------------------------------------------------------------------
extern "C" void kernel_launch(void* const* d_in, const int* in_sizes, int n_in,
                              void* d_out, int out_size)
{
    const float* x  = (const float*)d_in[0];
    const float* fl = (const float*)d_in[1];
    const float* fv = (const float*)d_in[2];
    const float* W0 = (const float*)d_in[3];
    const float* b0 = (const float*)d_in[4];
    const float* W1 = (const float*)d_in[5];
    const float* b1 = (const float*)d_in[6];
    const float* W2 = (const float*)d_in[7];
    const float* b2 = (const float*)d_in[8];
    const float* W3 = (const float*)d_in[9];
    const float* b3 = (const float*)d_in[10];
    const float* W4 = (const float*)d_in[11];
    const float* b4 = (const float*)d_in[12];
    float* out = (float*)d_out;

    cudaFuncSetAttribute(attn_mma_kernel, cudaFuncAttributeMaxDynamicSharedMemorySize, ATT_SMEM);
    cudaFuncSetAttribute(mlp_mma_kernel,  cudaFuncAttributeMaxDynamicSharedMemorySize, MLP_SMEM);

    prep_kernel<<<24, 256>>>(W0, W1, W2, W3, fv);
    attn_mma_kernel<<<N_PTS / 128, 256, ATT_SMEM>>>(x, fl);
    mlp_mma_kernel<<<N_PTS / 128, 256, MLP_SMEM>>>(b0, b1, b2, b3, W4, b4, out);
}